// round 1
// baseline (speedup 1.0000x reference)
#include <cuda_runtime.h>
#include <cstddef>

#define N_NODES 50000
#define N_EDGES 800000
#define D_NODE  128
#define D_EDGE  64
#define D_HID   128

// ---------------- scratch (device globals: no allocation allowed) ----------------
__device__ float    g_Q[N_NODES * D_NODE];
__device__ float    g_K[N_NODES * D_NODE];
__device__ float    g_V[N_NODES * D_NODE];
__device__ float    g_scores[N_EDGES];
__device__ float    g_expw[N_EDGES];
__device__ unsigned g_segmax[N_NODES];   // order-preserving-encoded float max
__device__ float    g_denom[N_NODES];

// ---------------- helpers ----------------
__device__ __forceinline__ float silu_f(float x) {
    return x / (1.0f + __expf(-x));
}
// monotonic float->uint encoding so unsigned atomicMax == float max
__device__ __forceinline__ unsigned enc_f(float f) {
    unsigned u = __float_as_uint(f);
    return (u & 0x80000000u) ? ~u : (u | 0x80000000u);
}
__device__ __forceinline__ float dec_f(unsigned u) {
    return __uint_as_float((u & 0x80000000u) ? (u & 0x7fffffffu) : ~u);
}

// ---------------- init: zero node_out region + softmax accumulators ----------------
__global__ void init_kernel(float* __restrict__ node_out) {
    int i = blockIdx.x * blockDim.x + threadIdx.x;
    if (i < N_NODES * D_NODE) node_out[i] = 0.0f;
    if (i < N_NODES) { g_segmax[i] = 0u; g_denom[i] = 0.0f; }
}

// ---------------- QKV GEMM: [50000,128] x [128,128] -> Q/K/V ----------------
// grid (ceil(N/64), 3), 256 threads. 64-row x 128-col tile per block, K chunked by 32.
__global__ void qkv_kernel(const float* __restrict__ node,
                           const float* __restrict__ Wq,
                           const float* __restrict__ Wk,
                           const float* __restrict__ Wv) {
    __shared__ float As[64 * 32];
    __shared__ float Ws[32 * 128];

    const float* W   = (blockIdx.y == 0) ? Wq : ((blockIdx.y == 1) ? Wk : Wv);
    float*       Out = (blockIdx.y == 0) ? g_Q : ((blockIdx.y == 1) ? g_K : g_V);

    const int r0  = blockIdx.x * 64;
    const int tid = threadIdx.x;
    const int rb  = tid >> 5;          // 0..7  -> rows rb*8..rb*8+7
    const int c   = tid & 31;          // 0..31 -> cols c*4..c*4+3

    float acc[8][4];
#pragma unroll
    for (int i = 0; i < 8; i++)
#pragma unroll
        for (int j = 0; j < 4; j++) acc[i][j] = 0.0f;

    for (int kk = 0; kk < 4; kk++) {
        __syncthreads();
        for (int idx = tid; idx < 64 * 32; idx += 256) {
            int r = idx >> 5, k = idx & 31;
            int gr = r0 + r;
            As[idx] = (gr < N_NODES) ? node[(size_t)gr * D_NODE + kk * 32 + k] : 0.0f;
        }
        for (int idx = tid; idx < 32 * 128; idx += 256) {
            int k = idx >> 7, cc = idx & 127;
            Ws[idx] = W[(size_t)(kk * 32 + k) * D_NODE + cc];
        }
        __syncthreads();

#pragma unroll 4
        for (int k = 0; k < 32; k++) {
            float4 w = *(const float4*)(Ws + k * 128 + c * 4);
#pragma unroll
            for (int i = 0; i < 8; i++) {
                float a = As[(rb * 8 + i) * 32 + k];
                acc[i][0] = fmaf(a, w.x, acc[i][0]);
                acc[i][1] = fmaf(a, w.y, acc[i][1]);
                acc[i][2] = fmaf(a, w.z, acc[i][2]);
                acc[i][3] = fmaf(a, w.w, acc[i][3]);
            }
        }
    }

#pragma unroll
    for (int i = 0; i < 8; i++) {
        int gr = r0 + rb * 8 + i;
        if (gr < N_NODES) {
            float4 o = make_float4(acc[i][0], acc[i][1], acc[i][2], acc[i][3]);
            *(float4*)(Out + (size_t)gr * D_NODE + c * 4) = o;
        }
    }
}

// ---------------- fused edge MLP: out = silu(silu(X@W1+b1)@W2+b2) ----------------
// grid 12500 blocks x 256 threads; each block: 64 edges. Dynamic smem ~113KB.
__global__ void mlp_kernel(const float* __restrict__ edge_feat,
                           const float* __restrict__ W1, const float* __restrict__ b1,
                           const float* __restrict__ W2, const float* __restrict__ b2,
                           float* __restrict__ edge_out) {
    extern __shared__ float sm[];
    float* W1s = sm;                 // 64*128 = 8192
    float* W2s = sm + 8192;          // 128*64 = 8192
    float* b1s = sm + 16384;         // 128
    float* b2s = sm + 16512;         // 64
    float* Xs  = sm + 16576;         // 64*64  = 4096
    float* Hs  = sm + 20672;         // 64*128 = 8192   (total 28864 floats)

    const int tid = threadIdx.x;
    const int e0  = blockIdx.x * 64;

    // load weights/biases + input tile (tile rows are contiguous: 64 edges * 64 feats)
    for (int i4 = tid; i4 < 2048; i4 += 256)
        ((float4*)W1s)[i4] = ((const float4*)W1)[i4];
    for (int i4 = tid; i4 < 2048; i4 += 256)
        ((float4*)W2s)[i4] = ((const float4*)W2)[i4];
    if (tid < 128) b1s[tid] = b1[tid];
    if (tid < 64)  b2s[tid] = b2[tid];
    for (int i4 = tid; i4 < 1024; i4 += 256)
        ((float4*)Xs)[i4] = ((const float4*)(edge_feat + (size_t)e0 * D_EDGE))[i4];
    __syncthreads();

    // ---- phase 1: H[64][128] = silu(X @ W1 + b1) ----
    {
        const int rb = tid >> 5;      // 0..7 -> rows rb*8..+7
        const int c4 = (tid & 31) * 4;
        float acc[8][4];
#pragma unroll
        for (int i = 0; i < 8; i++) {
            acc[i][0] = b1s[c4 + 0]; acc[i][1] = b1s[c4 + 1];
            acc[i][2] = b1s[c4 + 2]; acc[i][3] = b1s[c4 + 3];
        }
#pragma unroll 4
        for (int k = 0; k < 64; k++) {
            float4 w = *(const float4*)(W1s + k * 128 + c4);
#pragma unroll
            for (int i = 0; i < 8; i++) {
                float a = Xs[(rb * 8 + i) * 64 + k];
                acc[i][0] = fmaf(a, w.x, acc[i][0]);
                acc[i][1] = fmaf(a, w.y, acc[i][1]);
                acc[i][2] = fmaf(a, w.z, acc[i][2]);
                acc[i][3] = fmaf(a, w.w, acc[i][3]);
            }
        }
#pragma unroll
        for (int i = 0; i < 8; i++) {
            float4 h = make_float4(silu_f(acc[i][0]), silu_f(acc[i][1]),
                                   silu_f(acc[i][2]), silu_f(acc[i][3]));
            *(float4*)(Hs + (rb * 8 + i) * 128 + c4) = h;
        }
    }
    __syncthreads();

    // ---- phase 2: out[64][64] = silu(H @ W2 + b2) ----
    {
        const int rb = tid >> 4;      // 0..15 -> rows rb*4..+3
        const int c4 = (tid & 15) * 4;
        float acc[4][4];
#pragma unroll
        for (int i = 0; i < 4; i++) {
            acc[i][0] = b2s[c4 + 0]; acc[i][1] = b2s[c4 + 1];
            acc[i][2] = b2s[c4 + 2]; acc[i][3] = b2s[c4 + 3];
        }
#pragma unroll 4
        for (int k = 0; k < 128; k++) {
            float4 w = *(const float4*)(W2s + k * 64 + c4);
#pragma unroll
            for (int i = 0; i < 4; i++) {
                float a = Hs[(rb * 4 + i) * 128 + k];
                acc[i][0] = fmaf(a, w.x, acc[i][0]);
                acc[i][1] = fmaf(a, w.y, acc[i][1]);
                acc[i][2] = fmaf(a, w.z, acc[i][2]);
                acc[i][3] = fmaf(a, w.w, acc[i][3]);
            }
        }
#pragma unroll
        for (int i = 0; i < 4; i++) {
            float4 o = make_float4(silu_f(acc[i][0]), silu_f(acc[i][1]),
                                   silu_f(acc[i][2]), silu_f(acc[i][3]));
            *(float4*)(edge_out + (size_t)(e0 + rb * 4 + i) * D_EDGE + c4) = o;
        }
    }
}

// ---------------- attention pass 1: scores + segment max ----------------
// warp per edge; grid 100000 x 256
__global__ void score_kernel(const int* __restrict__ src, const int* __restrict__ dst) {
    int e = blockIdx.x * 8 + (threadIdx.x >> 5);
    int lane = threadIdx.x & 31;
    if (e >= N_EDGES) return;
    int d = dst[e], s = src[e];
    float4 q = *(const float4*)(g_Q + (size_t)d * D_NODE + lane * 4);
    float4 k = *(const float4*)(g_K + (size_t)s * D_NODE + lane * 4);
    float p = q.x * k.x + q.y * k.y + q.z * k.z + q.w * k.w;
#pragma unroll
    for (int off = 16; off > 0; off >>= 1) p += __shfl_xor_sync(0xffffffffu, p, off);
    if (lane == 0) {
        float sc = p / sqrtf(128.0f);
        g_scores[e] = sc;
        atomicMax(&g_segmax[d], enc_f(sc));
    }
}

// ---------------- pass 2: exp + segment sum ----------------
__global__ void expsum_kernel(const int* __restrict__ dst) {
    int e = blockIdx.x * blockDim.x + threadIdx.x;
    if (e >= N_EDGES) return;
    int d = dst[e];
    float m  = dec_f(g_segmax[d]);
    float ex = __expf(g_scores[e] - m);
    g_expw[e] = ex;
    atomicAdd(&g_denom[d], ex);
}

// ---------------- pass 3: alpha * V[src] scatter-sum ----------------
// warp per edge
__global__ void scatter_kernel(const int* __restrict__ src, const int* __restrict__ dst,
                               float* __restrict__ node_out) {
    int e = blockIdx.x * 8 + (threadIdx.x >> 5);
    int lane = threadIdx.x & 31;
    if (e >= N_EDGES) return;
    int d = dst[e], s = src[e];
    float alpha = g_expw[e] / g_denom[d];
    float4 v = *(const float4*)(g_V + (size_t)s * D_NODE + lane * 4);
    float* o = node_out + (size_t)d * D_NODE + lane * 4;
    atomicAdd(o + 0, alpha * v.x);
    atomicAdd(o + 1, alpha * v.y);
    atomicAdd(o + 2, alpha * v.z);
    atomicAdd(o + 3, alpha * v.w);
}

// ---------------- launch ----------------
extern "C" void kernel_launch(void* const* d_in, const int* in_sizes, int n_in,
                              void* d_out, int out_size) {
    const float* edge_feat = (const float*)d_in[0];
    const float* node_feat = (const float*)d_in[1];
    const int*   src       = (const int*)d_in[2];
    const int*   dst       = (const int*)d_in[3];
    const float* Wq        = (const float*)d_in[4];
    const float* Wk        = (const float*)d_in[5];
    const float* Wv        = (const float*)d_in[6];
    const float* W1        = (const float*)d_in[7];
    const float* b1        = (const float*)d_in[8];
    const float* W2        = (const float*)d_in[9];
    const float* b2        = (const float*)d_in[10];

    float* out      = (float*)d_out;
    float* edge_out = out;                                   // [800000 x 64]
    float* node_out = out + (size_t)N_EDGES * D_EDGE;        // [50000 x 128]

    // MLP kernel needs ~113KB dynamic smem
    const int mlp_smem = 28864 * (int)sizeof(float);
    cudaFuncSetAttribute(mlp_kernel, cudaFuncAttributeMaxDynamicSharedMemorySize, mlp_smem);

    init_kernel<<<(N_NODES * D_NODE + 255) / 256, 256>>>(node_out);

    dim3 gq((N_NODES + 63) / 64, 3);
    qkv_kernel<<<gq, 256>>>(node_feat, Wq, Wk, Wv);

    mlp_kernel<<<N_EDGES / 64, 256, mlp_smem>>>(edge_feat, W1, b1, W2, b2, edge_out);

    score_kernel<<<N_EDGES / 8, 256>>>(src, dst);
    expsum_kernel<<<(N_EDGES + 255) / 256, 256>>>(dst);
    scatter_kernel<<<N_EDGES / 8, 256>>>(src, dst, node_out);
}